// round 3
// baseline (speedup 1.0000x reference)
#include <cuda_runtime.h>

#define KK 9
#define TPB 256
#define GRID 1216
#define TILE TPB
#define TILE_F4 ((TILE * KK) / 4)   /* 576 float4 = 9216 B per tile */

__device__ float g_part[GRID];
__device__ unsigned g_ticket = 0;

__device__ __forceinline__ float ex2f(float x) { float r; asm("ex2.approx.f32 %0,%1;" : "=f"(r) : "f"(x)); return r; }
__device__ __forceinline__ float lg2f(float x) { float r; asm("lg2.approx.f32 %0,%1;" : "=f"(r) : "f"(x)); return r; }
__device__ __forceinline__ float rcpf(float x) { float r; asm("rcp.approx.f32 %0,%1;" : "=f"(r) : "f"(x)); return r; }

#define LOG2E 1.4426950408889634f
#define LN2   0.6931471805599453f

__global__ void __launch_bounds__(TPB)
loss_kernel(const float* __restrict__ logits, const int* __restrict__ y,
            float* __restrict__ out, int B, float invB) {
    __shared__ float4 s4[TILE_F4];          // 9216 B logits tile
    __shared__ float4 tbl[KK * KK];         // {tw, ctw=cw*[k<=y,k<8], fmask, 0}
    __shared__ float  wytab[KK];            // W_y = sum_{k<=min(y,7)} cw_k
    __shared__ float  wsum[TPB / 32];
    __shared__ int    s_last;
    float* sl = (float*)s4;

    // cdf weights (widths/95)
    const float cwv[KK] = {3.f/95.f, 7.f/95.f, 10.f/95.f, 10.f/95.f, 10.f/95.f,
                           10.f/95.f, 10.f/95.f, 10.f/95.f, 25.f/95.f};

    if (threadIdx.x < KK * KK) {
        int yy = threadIdx.x / KK, kk = threadIdx.x % KK;
        int d = kk - yy; if (d < 0) d = -d;
        int dm1 = d - 1;
        float tw = (d > 1) ? (float)(dm1 * dm1 * dm1) : 0.f;
        float fmask = (d > 1) ? 1.f : 0.f;
        float wk = (kk == 0) ? 3.f/95.f : (kk == 1) ? 7.f/95.f : (kk == 8) ? 25.f/95.f : 10.f/95.f;
        float ctw = (kk <= yy && kk < 8) ? wk : 0.f;
        tbl[threadIdx.x] = make_float4(tw, ctw, fmask, 0.f);
    }
    if (threadIdx.x < KK) {
        float s = 0.f;
        int lim = threadIdx.x < 7 ? threadIdx.x : 7;
        for (int k = 0; k <= lim; k++)
            s += (k == 0) ? 3.f/95.f : (k == 1) ? 7.f/95.f : 10.f/95.f;
        wytab[threadIdx.x] = s;
    }
    __syncthreads();

    int numTiles = B / TILE;
    float acc = 0.f;

    int t = blockIdx.x;
    float4 r0 = make_float4(0,0,0,0), r1 = r0, r2 = r0;
    bool valid = (t < numTiles);
    if (valid) {
        const float4* src = (const float4*)logits + (size_t)t * TILE_F4;
        r0 = src[threadIdx.x];
        r1 = src[threadIdx.x + TPB];
        if (threadIdx.x < TILE_F4 - 2 * TPB) r2 = src[threadIdx.x + 2 * TPB];
    }
    while (valid) {
        s4[threadIdx.x]       = r0;
        s4[threadIdx.x + TPB] = r1;
        if (threadIdx.x < TILE_F4 - 2 * TPB) s4[threadIdx.x + 2 * TPB] = r2;
        int yi = y[t * TILE + threadIdx.x];
        __syncthreads();

        // all smem reads for this row, before the protective barrier
        const float* lrow = sl + threadIdx.x * KK;    // stride 9: conflict-free
        float l[KK];
#pragma unroll
        for (int k = 0; k < KK; k++) l[k] = lrow[k];
        int il = yi - 1; if (il < 0) il = 0;
        int ir = yi + 1; if (ir > KK - 1) ir = KK - 1;
        float lyv = lrow[yi];
        float lL  = lrow[il];
        float lR  = lrow[ir];
        float4 tb[KK];
#pragma unroll
        for (int k = 0; k < KK; k++) tb[k] = tbl[yi * KK + k];
        float Wy = wytab[yi];
        __syncthreads();

        // prefetch next tile (overlaps compute)
        int tn = t + GRID;
        valid = tn < numTiles;
        if (valid) {
            const float4* src = (const float4*)logits + (size_t)tn * TILE_F4;
            r0 = src[threadIdx.x];
            r1 = src[threadIdx.x + TPB];
            if (threadIdx.x < TILE_F4 - 2 * TPB) r2 = src[threadIdx.x + 2 * TPB];
        }

        // ---- per-row loss (max-subtracted, deferred normalization) ----
        float m = l[0];
#pragma unroll
        for (int k = 1; k < KK; k++) m = fmaxf(m, l[k]);
        float mm = -m * LOG2E;

        float C = 0.f, tail_u = 0.f, far_u = 0.f, A = 0.f, Bm = 0.f;
#pragma unroll
        for (int k = 0; k < KK; k++) {
            float e = ex2f(fmaf(l[k], LOG2E, mm));
            C += e;
            tail_u = fmaf(e, tb[k].x, tail_u);
            far_u  = fmaxf(far_u, e * tb[k].z);
            if (k < KK - 1) {
                A  = fmaf(cwv[k], C * C, A);
                Bm = fmaf(tb[k].y, C, Bm);
            }
        }
        float S = C;
        float ey = ex2f(fmaf(lyv, LOG2E, mm));
        float aL = (yi > 0)      ? lL : -1e30f;
        float aR = (yi < KK - 1) ? lR : -1e30f;
        float en = ex2f(fmaf(fmaxf(aL, aR), LOG2E, mm));

        float invS = rcpf(S);
        float nll  = fmaf(lg2f(S), LN2, m) - lyv;
        float py   = ey * invS;
        float fm   = fmaxf(fmaf(far_u, invS, 0.15f - py), 0.f);
        float lp   = fmaxf(fmaf(en,    invS, 0.35f - py), 0.f);
        float emd_u = fmaf(Wy, S * S, fmaf(Bm, -(S + S), A));

        float r = fmaf(nll, 0.45511961331341866f, 2.8f * fm);
        r = fmaf(tail_u * invS, 3.6f, r);
        r = fmaf(lp, 4.8f, r);
        r = fmaf(emd_u * invS * invS, 0.48f, r);
        acc += r;

        t = tn;
    }

    // remainder rows (B % TILE) — block 0, direct global loads
    int rem = numTiles * TILE;
    if (blockIdx.x == 0) {
        int row = rem + threadIdx.x;
        if (row < B) {
            float l[KK];
#pragma unroll
            for (int k = 0; k < KK; k++) l[k] = logits[(size_t)row * KK + k];
            int yi = y[row];
            float m = l[0];
#pragma unroll
            for (int k = 1; k < KK; k++) m = fmaxf(m, l[k]);
            float mm = -m * LOG2E;
            float C = 0.f, tail_u = 0.f, far_u = 0.f, A = 0.f, Bm = 0.f;
#pragma unroll
            for (int k = 0; k < KK; k++) {
                float e = ex2f(fmaf(l[k], LOG2E, mm));
                C += e;
                float4 tv = tbl[yi * KK + k];
                tail_u = fmaf(e, tv.x, tail_u);
                far_u  = fmaxf(far_u, e * tv.z);
                if (k < KK - 1) {
                    A  = fmaf(cwv[k], C * C, A);
                    Bm = fmaf(tv.y, C, Bm);
                }
            }
            float S = C;
            float lyv = l[0];
#pragma unroll
            for (int k = 1; k < KK; k++) lyv = (k == yi) ? l[k] : lyv;
            float aL = -1e30f, aR = -1e30f;
#pragma unroll
            for (int k = 0; k < KK; k++) {
                aL = (k == yi - 1) ? l[k] : aL;
                aR = (k == yi + 1) ? l[k] : aR;
            }
            float ey = ex2f(fmaf(lyv, LOG2E, mm));
            float en = ex2f(fmaf(fmaxf(aL, aR), LOG2E, mm));
            float invS = rcpf(S);
            float nll  = fmaf(lg2f(S), LN2, m) - lyv;
            float py   = ey * invS;
            float fmv  = fmaxf(fmaf(far_u, invS, 0.15f - py), 0.f);
            float lpv  = fmaxf(fmaf(en,    invS, 0.35f - py), 0.f);
            float emd_u = fmaf(wytab[yi], S * S, fmaf(Bm, -(S + S), A));
            float r = fmaf(nll, 0.45511961331341866f, 2.8f * fmv);
            r = fmaf(tail_u * invS, 3.6f, r);
            r = fmaf(lpv, 4.8f, r);
            r = fmaf(emd_u * invS * invS, 0.48f, r);
            acc += r;
        }
    }

    // deterministic block reduction
#pragma unroll
    for (int o = 16; o > 0; o >>= 1) acc += __shfl_xor_sync(0xffffffffu, acc, o);
    if ((threadIdx.x & 31) == 0) wsum[threadIdx.x >> 5] = acc;
    __syncthreads();
    if (threadIdx.x == 0) {
        float s = 0.f;
#pragma unroll
        for (int i = 0; i < TPB / 32; i++) s += wsum[i];
        g_part[blockIdx.x] = s;
        __threadfence();
        unsigned tk = atomicAdd(&g_ticket, 1u);
        s_last = (tk == GRID - 1);
    }
    __syncthreads();

    if (s_last) {
        float s = 0.f;
        for (int i = threadIdx.x; i < GRID; i += TPB) s += __ldcg(&g_part[i]);
#pragma unroll
        for (int o = 16; o > 0; o >>= 1) s += __shfl_xor_sync(0xffffffffu, s, o);
        if ((threadIdx.x & 31) == 0) wsum[threadIdx.x >> 5] = s;
        __syncthreads();
        if (threadIdx.x == 0) {
            float tt = 0.f;
#pragma unroll
            for (int i = 0; i < TPB / 32; i++) tt += wsum[i];
            out[0] = tt * invB;
            g_ticket = 0;   // deterministic across graph replays
        }
    }
}

extern "C" void kernel_launch(void* const* d_in, const int* in_sizes, int n_in,
                              void* d_out, int out_size) {
    const float* logits = (const float*)d_in[0];
    const int*   y      = (const int*)d_in[1];
    int B = in_sizes[1];
    loss_kernel<<<GRID, TPB>>>(logits, y, (float*)d_out, B, 1.f / (float)B);
}

// round 6
// speedup vs baseline: 1.2741x; 1.2741x over previous
#include <cuda_runtime.h>

#define KK 9
#define TPB 256
#define GRID 1216
#define TILE TPB
#define TILE_N (TILE * KK)          /* 2304 floats per tile */
#define TILE_F4 (TILE_N / 4)        /* 576 float4 = 9216 B   */

__device__ float g_part[GRID];
__device__ unsigned g_ticket = 0;

__device__ __forceinline__ float ex2f(float x) { float r; asm("ex2.approx.f32 %0,%1;" : "=f"(r) : "f"(x)); return r; }
__device__ __forceinline__ float lg2f(float x) { float r; asm("lg2.approx.f32 %0,%1;" : "=f"(r) : "f"(x)); return r; }
__device__ __forceinline__ float rcpf(float x) { float r; asm("rcp.approx.f32 %0,%1;" : "=f"(r) : "f"(x)); return r; }

#define LOG2E 1.4426950408889634f
#define LN2   0.6931471805599453f

// Per-row loss. l[9] logits, yi label, lyv=l[yi], aL/aR neighbor logits (-1e30 if absent).
// stw: smem tail-weight table (81 floats), Wy = sum_{k<=y} cw_k (includes k=8!).
__device__ __forceinline__ float row_loss(const float* l, int yi, float lyv,
                                          float aL, float aR,
                                          const float* stw, float Wy) {
    const float cwv[KK] = {3.f/95.f, 7.f/95.f, 10.f/95.f, 10.f/95.f, 10.f/95.f,
                           10.f/95.f, 10.f/95.f, 10.f/95.f, 25.f/95.f};
    float m = l[0];
#pragma unroll
    for (int k = 1; k < KK; k++) m = fmaxf(m, l[k]);
    float mm = -m * LOG2E;

    const float* tw = stw + yi * KK;       // 9 distinct banks across yi: conflict-free
    float C = 0.f, tail_u = 0.f, far_u = 0.f, A = 0.f, Bm = 0.f;
#pragma unroll
    for (int k = 0; k < KK; k++) {
        float e = ex2f(fmaf(l[k], LOG2E, mm));   // exp(l_k - m)
        C += e;
        float w = tw[k];
        tail_u = fmaf(e, w, tail_u);
        if (w > 0.f) far_u = fmaxf(far_u, e);    // far mask == (tw>0), free predicate
        A = fmaf(cwv[k], C * C, A);              // EMD expanded: sum cw*C^2 (all 9 k)
        if (k <= yi) Bm = fmaf(cwv[k], C, Bm);   // sum_{k<=y} cw*C
    }
    float S = C;
    float ey = ex2f(fmaf(lyv, LOG2E, mm));       // bitwise == e[yi]
    float en = ex2f(fmaf(fmaxf(aL, aR), LOG2E, mm));

    float invS = rcpf(S);
    float nll  = fmaf(lg2f(S), LN2, m) - lyv;    // log-sum-exp - l_y
    float py   = ey * invS;
    float fm   = fmaxf(fmaf(far_u, invS, 0.15f - py), 0.f);
    float lp   = fmaxf(fmaf(en,    invS, 0.35f - py), 0.f);
    // emd = (A - 2*S*Bm + Wy*S^2) / S^2   (k=8 term included: cw8 when y<8)
    float emd_u = fmaf(Wy, S * S, fmaf(Bm, -(S + S), A));

    float r = fmaf(nll, 0.45511961331341866f, 2.8f * fm);
    r = fmaf(tail_u * invS, 3.6f, r);
    r = fmaf(lp, 4.8f, r);
    r = fmaf(emd_u * invS * invS, 0.48f, r);
    return r;
}

__global__ void __launch_bounds__(TPB)
loss_kernel(const float* __restrict__ logits, const int* __restrict__ y,
            float* __restrict__ out, int B, float invB) {
    __shared__ float sbuf[2][TILE_N];      // double-buffered logits tiles (2x9216B)
    __shared__ float stw[KK * KK];
    __shared__ float swy[KK];
    __shared__ float wsum[TPB / 32];
    __shared__ int   s_last;

    int tid = threadIdx.x;

    if (tid < KK * KK) {
        int yy = tid / KK, kk = tid % KK;
        int d = kk - yy; if (d < 0) d = -d;
        int dm1 = d - 1;
        stw[tid] = (d > 1) ? (float)(dm1 * dm1 * dm1) : 0.f;
    }
    if (tid < KK) {
        float s = 0.f;
        for (int k = 0; k <= tid; k++)
            s += (k == 0) ? 3.f/95.f : (k == 1) ? 7.f/95.f : (k == 8) ? 25.f/95.f : 10.f/95.f;
        swy[tid] = s;   // includes k=8: swy[8] = 1
    }

    int numTiles = B / TILE;
    float acc = 0.f;

    int t = blockIdx.x;
    bool valid = (t < numTiles);
    float4 r0 = make_float4(0,0,0,0), r1 = r0, r2 = r0;
    int yc = 0;

    // prologue: stage tile t into buf0; prefetch tile t+GRID into regs
    if (valid) {
        const float4* src = (const float4*)logits + (size_t)t * TILE_F4;
        float4 a0 = src[tid];
        float4 a1 = src[tid + TPB];
        float4 a2 = (tid < TILE_F4 - 2*TPB) ? src[tid + 2*TPB] : make_float4(0,0,0,0);
        float4* dst = (float4*)sbuf[0];
        dst[tid] = a0; dst[tid + TPB] = a1;
        if (tid < TILE_F4 - 2*TPB) dst[tid + 2*TPB] = a2;
        yc = y[t * TILE + tid];
    }
    int tn = t + GRID;
    bool vnext = (tn < numTiles);
    int yn = 0;
    if (vnext) {
        const float4* src = (const float4*)logits + (size_t)tn * TILE_F4;
        r0 = src[tid];
        r1 = src[tid + TPB];
        if (tid < TILE_F4 - 2*TPB) r2 = src[tid + 2*TPB];
        yn = y[tn * TILE + tid];
    }
    __syncthreads();   // tables + buf0 ready

    int cur = 0;
    while (valid) {
        // ---- all reads of buf[cur] happen BEFORE the barrier ----
        const float* lrow = sbuf[cur] + tid * KK;   // stride 9: conflict-free
        float l[KK];
#pragma unroll
        for (int k = 0; k < KK; k++) l[k] = lrow[k];
        int yi = yc;
        int il = yi - 1; if (il < 0) il = 0;
        int ir = yi + 1; if (ir > KK - 1) ir = KK - 1;
        float lyv = lrow[yi];
        float aL = (yi > 0)      ? lrow[il] : -1e30f;
        float aR = (yi < KK - 1) ? lrow[ir] : -1e30f;

        // stage prefetched tile tn into the OTHER buffer
        if (vnext) {
            float* dst = sbuf[cur ^ 1];
            float4* d4 = (float4*)dst;
            d4[tid] = r0; d4[tid + TPB] = r1;
            if (tid < TILE_F4 - 2*TPB) d4[tid + 2*TPB] = r2;
        }
        // prefetch tile tn+GRID into regs (overlaps compute + barrier)
        int tnn = tn + GRID;
        bool vnn = vnext && (tnn < numTiles);
        if (vnn) {
            const float4* src = (const float4*)logits + (size_t)tnn * TILE_F4;
            r0 = src[tid];
            r1 = src[tid + TPB];
            if (tid < TILE_F4 - 2*TPB) r2 = src[tid + 2*TPB];
        }
        yc = yn;
        if (vnn) yn = y[tnn * TILE + tid];
        __syncthreads();   // one barrier per tile

        acc += row_loss(l, yi, lyv, aL, aR, stw, swy[yi]);

        t = tn; tn = tnn; valid = vnext; vnext = vnn; cur ^= 1;
    }

    // remainder rows (B % TILE) — block 0, direct global loads
    int rem = numTiles * TILE;
    if (blockIdx.x == 0) {
        int row = rem + tid;
        if (row < B) {
            float l[KK];
#pragma unroll
            for (int k = 0; k < KK; k++) l[k] = logits[(size_t)row * KK + k];
            int yi = y[row];
            float lyv = l[0], aL = -1e30f, aR = -1e30f;
#pragma unroll
            for (int k = 0; k < KK; k++) {
                lyv = (k == yi)     ? l[k] : lyv;
                aL  = (k == yi - 1) ? l[k] : aL;
                aR  = (k == yi + 1) ? l[k] : aR;
            }
            acc += row_loss(l, yi, lyv, aL, aR, stw, swy[yi]);
        }
    }

    // deterministic block reduction
#pragma unroll
    for (int o = 16; o > 0; o >>= 1) acc += __shfl_xor_sync(0xffffffffu, acc, o);
    if ((tid & 31) == 0) wsum[tid >> 5] = acc;
    __syncthreads();
    if (tid == 0) {
        float s = 0.f;
#pragma unroll
        for (int i = 0; i < TPB / 32; i++) s += wsum[i];
        g_part[blockIdx.x] = s;
        __threadfence();
        unsigned tk = atomicAdd(&g_ticket, 1u);
        s_last = (tk == GRID - 1);
    }
    __syncthreads();

    if (s_last) {
        __threadfence();   // acquire: order partial reads after ticket observation
        float s = 0.f;
        for (int i = tid; i < GRID; i += TPB) s += __ldcg(&g_part[i]);
#pragma unroll
        for (int o = 16; o > 0; o >>= 1) s += __shfl_xor_sync(0xffffffffu, s, o);
        if ((tid & 31) == 0) wsum[tid >> 5] = s;
        __syncthreads();
        if (tid == 0) {
            float tt = 0.f;
#pragma unroll
            for (int i = 0; i < TPB / 32; i++) tt += wsum[i];
            out[0] = tt * invB;
            g_ticket = 0;   // deterministic across graph replays
        }
    }
}

extern "C" void kernel_launch(void* const* d_in, const int* in_sizes, int n_in,
                              void* d_out, int out_size) {
    const float* logits = (const float*)d_in[0];
    const int*   y      = (const int*)d_in[1];
    int B = in_sizes[1];
    loss_kernel<<<GRID, TPB>>>(logits, y, (float*)d_out, B, 1.f / (float)B);
}